// round 4
// baseline (speedup 1.0000x reference)
#include <cuda_runtime.h>
#include <cuda_fp16.h>

// Problem constants (fixed-shape problem)
#define NB      32
#define NSITES  65536
#define NNGB    13
#define DIM     3
#define NG      48
#define KDIM    (NG * DIM)             // 144
#define NPREP   16
#define ROWS_PER_PREP (KDIM / NPREP)   // 9
#define SITES_PER_BLK 64
#define CONV_THREADS  256

// Scratch (device-global: allocation-free rule)
__device__ __align__(16) __half g_InTh[NSITES * NB];   // 4 MB, fp16 site-major transpose
__device__ float g_Wpart[NPREP][DIM * NNGB];
__device__ float g_Wmean[DIM * NNGB];

// ---------------------------------------------------------------------------
// Kernel 1: partial Wmean. 16 blocks x 320 threads; block p handles gdiags
// rows [9p, 9p+9). B[k][j] = wtVC[k%3][GnnPerms[k/3][j]].
// ---------------------------------------------------------------------------
__global__ __launch_bounds__(320)
void prep_kernel(const float* __restrict__ wtVC,
                 const float* __restrict__ gdiags,
                 const int*   __restrict__ GnnPerms) {
    __shared__ float B[KDIM][NNGB];
    __shared__ float sW[DIM * NNGB];
    int tid = threadIdx.x;

    if (tid < DIM * NNGB) sW[tid] = 0.f;
    for (int i = tid; i < KDIM * NNGB; i += 320) {
        int k = i / NNGB, j = i % NNGB;
        B[k][j] = wtVC[(k % 3) * NNGB + GnnPerms[(k / 3) * NNGB + j]];
    }
    __syncthreads();

    int w = tid >> 5, lane = tid & 31;
    if (w < ROWS_PER_PREP) {
        int r = blockIdx.x * ROWS_PER_PREP + w;
        float acc[NNGB];
        #pragma unroll
        for (int j = 0; j < NNGB; j++) acc[j] = 0.f;
        for (int k = lane; k < KDIM; k += 32) {            // coalesced row read
            float gv = gdiags[r * KDIM + k];
            #pragma unroll
            for (int j = 0; j < NNGB; j++) acc[j] += gv * B[k][j];
        }
        #pragma unroll
        for (int j = 0; j < NNGB; j++) {
            #pragma unroll
            for (int off = 16; off > 0; off >>= 1)
                acc[j] += __shfl_xor_sync(0xffffffffu, acc[j], off);
        }
        if (lane == 0) {
            int d = r % 3;
            #pragma unroll
            for (int j = 0; j < NNGB; j++)
                atomicAdd(&sW[d * NNGB + j], acc[j]);
        }
    }
    __syncthreads();
    if (tid < DIM * NNGB) g_Wpart[blockIdx.x][tid] = sW[tid];
}

// ---------------------------------------------------------------------------
// Kernel 2: transpose In (NB x NSITES, fp32) -> g_InTh (NSITES x NB, fp16).
// Block 0 additionally reduces Wmean partials (prep done: stream order).
// ---------------------------------------------------------------------------
__global__ void transpose_kernel(const float* __restrict__ In) {
    __shared__ float tile[32][33];
    int tx = threadIdx.x, ty = threadIdx.y;
    int tid = ty * 32 + tx;

    if (blockIdx.x == 0 && tid < DIM * NNGB) {
        float s = 0.f;
        #pragma unroll
        for (int p = 0; p < NPREP; p++) s += g_Wpart[p][tid];
        g_Wmean[tid] = s * (1.0f / (float)NG);
    }

    int s0 = blockIdx.x * 32;
    tile[ty][tx] = In[ty * NSITES + s0 + tx];              // coalesced read
    __syncthreads();
    g_InTh[(s0 + ty) * NB + tx] = __float2half(tile[tx][ty]);  // coalesced 2B/thread
}

// ---------------------------------------------------------------------------
// Kernel 3: gather + contraction, fp16 input / fp32 accumulate.
// Block = 256 threads, 64 sites. Lane l: site = 8*w + (l>>2), chunk c = l&3
// (16B = batches 8c..8c+7). One warp-gather covers 8 sites (8 x 64B rows).
// ---------------------------------------------------------------------------
__global__ __launch_bounds__(CONV_THREADS, 8)
void conv_kernel(const int* __restrict__ NNsites, float* __restrict__ out) {
    __shared__ float Wm[40];
    __shared__ int   sidx[NNGB][SITES_PER_BLK];
    __shared__ float sout[DIM][NB][SITES_PER_BLK + 1];  // pad 65 -> conflict-free

    int tid = threadIdx.x;
    int s0  = blockIdx.x * SITES_PER_BLK;

    if (tid < DIM * NNGB) Wm[tid] = g_Wmean[tid];
    for (int i = tid; i < NNGB * SITES_PER_BLK; i += CONV_THREADS) {
        int j = i >> 6, si = i & 63;
        sidx[j][si] = NNsites[j * NSITES + s0 + si];    // coalesced
    }
    __syncthreads();

    int w    = tid >> 5;
    int l    = tid & 31;
    int site = (w << 3) + (l >> 2);   // 0..63
    int c    = l & 3;                 // 16B chunk -> batches 8c..8c+7

    const uint4* __restrict__ InT16 = (const uint4*)g_InTh;

    float2 a0[4], a1[4], a2[4];       // [dim][half2-pair], batches 8c..8c+7
    #pragma unroll
    for (int q = 0; q < 4; q++) {
        a0[q] = make_float2(0.f, 0.f);
        a1[q] = make_float2(0.f, 0.f);
        a2[q] = make_float2(0.f, 0.f);
    }

    #pragma unroll
    for (int j = 0; j < NNGB; j++) {
        int   t  = sidx[j][site];
        uint4 rv = __ldg(&InT16[t * 4 + c]);       // 64B-row gather, 16B/lane
        float2 v[4];
        v[0] = __half22float2(*reinterpret_cast<__half2*>(&rv.x));
        v[1] = __half22float2(*reinterpret_cast<__half2*>(&rv.y));
        v[2] = __half22float2(*reinterpret_cast<__half2*>(&rv.z));
        v[3] = __half22float2(*reinterpret_cast<__half2*>(&rv.w));
        float w0 = Wm[j], w1 = Wm[NNGB + j], w2 = Wm[2 * NNGB + j];
        #pragma unroll
        for (int q = 0; q < 4; q++) {
            a0[q].x += w0 * v[q].x; a0[q].y += w0 * v[q].y;
            a1[q].x += w1 * v[q].x; a1[q].y += w1 * v[q].y;
            a2[q].x += w2 * v[q].x; a2[q].y += w2 * v[q].y;
        }
    }

    // Stage. Bank of sout[d][b][site] = (b + site) mod 32 (65 ≡ 1 mod 32);
    // per store-slot lanes have b=8c+const, site=8w+r -> 8c+r distinct mod 32.
    int b0 = c << 3;
    #pragma unroll
    for (int q = 0; q < 4; q++) {
        sout[0][b0 + 2 * q][site]     = a0[q].x;
        sout[0][b0 + 2 * q + 1][site] = a0[q].y;
        sout[1][b0 + 2 * q][site]     = a1[q].x;
        sout[1][b0 + 2 * q + 1][site] = a1[q].y;
        sout[2][b0 + 2 * q][site]     = a2[q].x;
        sout[2][b0 + 2 * q + 1][site] = a2[q].y;
    }
    __syncthreads();

    // Write out[b][d][s0+si]: 6144 floats/block, 24 per thread.
    // Warp spans 32 consecutive si with fixed (b,d): coalesced 128B stores.
    #pragma unroll
    for (int k = 0; k < 24; k++) {
        int idx  = tid + (k << 8);
        int si   = idx & 63;
        int rest = idx >> 6;          // 0..95
        int d    = rest % 3;
        int b    = rest / 3;
        out[(b * DIM + d) * NSITES + s0 + si] = sout[d][b][si];
    }
}

// ---------------------------------------------------------------------------
// Launch: In, wtVC, gdiags, GnnPerms, NNsites (metadata order)
// ---------------------------------------------------------------------------
extern "C" void kernel_launch(void* const* d_in, const int* in_sizes, int n_in,
                              void* d_out, int out_size) {
    const float* In       = (const float*)d_in[0];
    const float* wtVC     = (const float*)d_in[1];
    const float* gdiags   = (const float*)d_in[2];
    const int*   GnnPerms = (const int*)  d_in[3];
    const int*   NNsites  = (const int*)  d_in[4];
    float*       out      = (float*)d_out;

    prep_kernel<<<NPREP, 320>>>(wtVC, gdiags, GnnPerms);

    dim3 tblk(32, 32);
    transpose_kernel<<<NSITES / 32, tblk>>>(In);

    conv_kernel<<<NSITES / SITES_PER_BLK, CONV_THREADS>>>(NNsites, out);
}

// round 5
// speedup vs baseline: 2.0670x; 2.0670x over previous
#include <cuda_runtime.h>
#include <cuda_fp16.h>

// Problem constants (fixed-shape problem)
#define NB      32
#define NSITES  65536
#define NNGB    13
#define DIM     3
#define NG      48
#define KDIM    (NG * DIM)             // 144
#define NPREP   16
#define ROWS_PER_PREP (KDIM / NPREP)   // 9
#define SITES_PER_BLK 64
#define CONV_THREADS  256

// Scratch (device-global: allocation-free rule)
__device__ __align__(16) __half g_InTh[NSITES * NB];   // 4 MB, fp16 site-major transpose
__device__ float g_Wpart[NPREP][DIM * NNGB];
__device__ float g_Wmean[DIM * NNGB];

// ---------------------------------------------------------------------------
// Kernel 1: partial Wmean. 16 blocks x 320 threads; block p handles gdiags
// rows [9p, 9p+9). B[k][j] = wtVC[k%3][GnnPerms[k/3][j]].
// ---------------------------------------------------------------------------
__global__ __launch_bounds__(320)
void prep_kernel(const float* __restrict__ wtVC,
                 const float* __restrict__ gdiags,
                 const int*   __restrict__ GnnPerms) {
    __shared__ float B[KDIM][NNGB];
    __shared__ float sW[DIM * NNGB];
    int tid = threadIdx.x;

    if (tid < DIM * NNGB) sW[tid] = 0.f;
    for (int i = tid; i < KDIM * NNGB; i += 320) {
        int k = i / NNGB, j = i % NNGB;
        B[k][j] = wtVC[(k % 3) * NNGB + GnnPerms[(k / 3) * NNGB + j]];
    }
    __syncthreads();

    int w = tid >> 5, lane = tid & 31;
    if (w < ROWS_PER_PREP) {
        int r = blockIdx.x * ROWS_PER_PREP + w;
        float acc[NNGB];
        #pragma unroll
        for (int j = 0; j < NNGB; j++) acc[j] = 0.f;
        for (int k = lane; k < KDIM; k += 32) {            // coalesced row read
            float gv = gdiags[r * KDIM + k];
            #pragma unroll
            for (int j = 0; j < NNGB; j++) acc[j] += gv * B[k][j];
        }
        #pragma unroll
        for (int j = 0; j < NNGB; j++) {
            #pragma unroll
            for (int off = 16; off > 0; off >>= 1)
                acc[j] += __shfl_xor_sync(0xffffffffu, acc[j], off);
        }
        if (lane == 0) {
            int d = r % 3;
            #pragma unroll
            for (int j = 0; j < NNGB; j++)
                atomicAdd(&sW[d * NNGB + j], acc[j]);
        }
    }
    __syncthreads();
    if (tid < DIM * NNGB) g_Wpart[blockIdx.x][tid] = sW[tid];
}

// ---------------------------------------------------------------------------
// Kernel 2: transpose In (NB x NSITES, fp32) -> g_InTh (NSITES x NB, fp16).
// Block 0 additionally reduces Wmean partials (prep done: stream order).
// ---------------------------------------------------------------------------
__global__ void transpose_kernel(const float* __restrict__ In) {
    __shared__ float tile[32][33];
    int tx = threadIdx.x, ty = threadIdx.y;
    int tid = ty * 32 + tx;

    if (blockIdx.x == 0 && tid < DIM * NNGB) {
        float s = 0.f;
        #pragma unroll
        for (int p = 0; p < NPREP; p++) s += g_Wpart[p][tid];
        g_Wmean[tid] = s * (1.0f / (float)NG);
    }

    int s0 = blockIdx.x * 32;
    tile[ty][tx] = In[ty * NSITES + s0 + tx];              // coalesced read
    __syncthreads();
    g_InTh[(s0 + ty) * NB + tx] = __float2half(tile[tx][ty]);  // coalesced 2B/thread
}

// ---------------------------------------------------------------------------
// Kernel 3: gather + contraction, fp16 input / fp32 accumulate.
// Block = 256 threads, 64 sites. Lane l: site = 8*w + (l>>2), chunk c = l&3
// (16B = batches 8c..8c+7). One warp-gather covers 8 sites (8 x 64B rows).
// NOTE: occupancy target 4 (not 8) -> 64-reg budget, NO spills (24 live
// fp32 accumulators). Round-4's (256,8) forced 32 regs and spilled in-loop.
// ---------------------------------------------------------------------------
__global__ __launch_bounds__(CONV_THREADS, 4)
void conv_kernel(const int* __restrict__ NNsites, float* __restrict__ out) {
    __shared__ float Wm[40];
    __shared__ int   sidx[NNGB][SITES_PER_BLK];
    __shared__ float sout[DIM][NB][SITES_PER_BLK + 1];  // pad 65 -> conflict-free

    int tid = threadIdx.x;
    int s0  = blockIdx.x * SITES_PER_BLK;

    if (tid < DIM * NNGB) Wm[tid] = g_Wmean[tid];
    for (int i = tid; i < NNGB * SITES_PER_BLK; i += CONV_THREADS) {
        int j = i >> 6, si = i & 63;
        sidx[j][si] = NNsites[j * NSITES + s0 + si];    // coalesced
    }
    __syncthreads();

    int w    = tid >> 5;
    int l    = tid & 31;
    int site = (w << 3) + (l >> 2);   // 0..63
    int c    = l & 3;                 // 16B chunk -> batches 8c..8c+7

    const uint4* __restrict__ InT16 = (const uint4*)g_InTh;

    float2 a0[4], a1[4], a2[4];       // [dim][half2-pair], batches 8c..8c+7
    #pragma unroll
    for (int q = 0; q < 4; q++) {
        a0[q] = make_float2(0.f, 0.f);
        a1[q] = make_float2(0.f, 0.f);
        a2[q] = make_float2(0.f, 0.f);
    }

    #pragma unroll
    for (int j = 0; j < NNGB; j++) {
        int   t  = sidx[j][site];
        uint4 rv = __ldg(&InT16[t * 4 + c]);       // 64B-row gather, 16B/lane
        float2 v[4];
        v[0] = __half22float2(*reinterpret_cast<__half2*>(&rv.x));
        v[1] = __half22float2(*reinterpret_cast<__half2*>(&rv.y));
        v[2] = __half22float2(*reinterpret_cast<__half2*>(&rv.z));
        v[3] = __half22float2(*reinterpret_cast<__half2*>(&rv.w));
        float w0 = Wm[j], w1 = Wm[NNGB + j], w2 = Wm[2 * NNGB + j];
        #pragma unroll
        for (int q = 0; q < 4; q++) {
            a0[q].x += w0 * v[q].x; a0[q].y += w0 * v[q].y;
            a1[q].x += w1 * v[q].x; a1[q].y += w1 * v[q].y;
            a2[q].x += w2 * v[q].x; a2[q].y += w2 * v[q].y;
        }
    }

    // Stage. Bank of sout[d][b][site] = (b + site) mod 32 (65 ≡ 1 mod 32);
    // per store-slot lanes have b=8c+const, site=8w+r -> 8c+r distinct mod 32.
    int b0 = c << 3;
    #pragma unroll
    for (int q = 0; q < 4; q++) {
        sout[0][b0 + 2 * q][site]     = a0[q].x;
        sout[0][b0 + 2 * q + 1][site] = a0[q].y;
        sout[1][b0 + 2 * q][site]     = a1[q].x;
        sout[1][b0 + 2 * q + 1][site] = a1[q].y;
        sout[2][b0 + 2 * q][site]     = a2[q].x;
        sout[2][b0 + 2 * q + 1][site] = a2[q].y;
    }
    __syncthreads();

    // Write out[b][d][s0+si]: 6144 floats/block, 24 per thread.
    // Warp spans 32 consecutive si with fixed (b,d): coalesced 128B stores.
    #pragma unroll
    for (int k = 0; k < 24; k++) {
        int idx  = tid + (k << 8);
        int si   = idx & 63;
        int rest = idx >> 6;          // 0..95
        int d    = rest % 3;
        int b    = rest / 3;
        out[(b * DIM + d) * NSITES + s0 + si] = sout[d][b][si];
    }
}

// ---------------------------------------------------------------------------
// Launch: In, wtVC, gdiags, GnnPerms, NNsites (metadata order)
// ---------------------------------------------------------------------------
extern "C" void kernel_launch(void* const* d_in, const int* in_sizes, int n_in,
                              void* d_out, int out_size) {
    const float* In       = (const float*)d_in[0];
    const float* wtVC     = (const float*)d_in[1];
    const float* gdiags   = (const float*)d_in[2];
    const int*   GnnPerms = (const int*)  d_in[3];
    const int*   NNsites  = (const int*)  d_in[4];
    float*       out      = (float*)d_out;

    prep_kernel<<<NPREP, 320>>>(wtVC, gdiags, GnnPerms);

    dim3 tblk(32, 32);
    transpose_kernel<<<NSITES / 32, tblk>>>(In);

    conv_kernel<<<NSITES / SITES_PER_BLK, CONV_THREADS>>>(NNsites, out);
}